// round 5
// baseline (speedup 1.0000x reference)
#include <cuda_runtime.h>
#include <math.h>

#define EMB 1024
#define HID 1024
#define SEQ 2048
#define NEMO 16
#define LABELS 7
#define G4 (4*HID)

#define NB 128        // blocks in sequential kernel (<= 148 SMs -> co-resident)
#define JPB (HID/NB)  // 8 hidden units per block
#define TPB 256

// ---------------- static device scratch (no allocations allowed) ----------------
struct SeqState {
    unsigned counter;
    unsigned pad[31];
    float h[2][HID];     // double-buffered hidden state
};

__device__ float g_Xb[SEQ * EMB];       // gathered word embeddings  (8 MB)
__device__ float g_C [SEQ * EMB];       // relu(comb) per step       (8 MB)
__device__ float g_G [SEQ * G4];        // W_ih @ C + b_ih + b_hh    (32 MB)
__device__ float g_emoji[EMB];
__device__ float g_const2[EMB];         // We @ emoji_ave + comb_b
__device__ float g_bsum[G4];            // b_ih + b_hh
__device__ SeqState g_st;

// ---------------- small kernels ----------------
__global__ void k_init() {
    if (threadIdx.x == 0) g_st.counter = 0u;
    float* h = &g_st.h[0][0];
    for (int i = threadIdx.x; i < 2 * HID; i += blockDim.x) h[i] = 0.f;
}

__global__ void k_emoji(const int* __restrict__ eids, const float* __restrict__ eemb) {
    int e = blockIdx.x * blockDim.x + threadIdx.x;
    if (e < EMB) {
        float s = 0.f;
        #pragma unroll
        for (int n = 0; n < NEMO; n++)
            s += eemb[(size_t)eids[n] * EMB + e];
        g_emoji[e] = s * (1.0f / NEMO);
    }
}

// const2[i] = dot(comb_W[i, EMB:2*EMB], emoji_ave) + comb_b[i]; warp per row
__global__ void k_const2(const float* __restrict__ combW, const float* __restrict__ combB) {
    int warp = threadIdx.x >> 5, lane = threadIdx.x & 31;
    int row = blockIdx.x * 8 + warp;
    const float* wr = combW + (size_t)row * (2 * EMB) + EMB;
    float s = 0.f;
    for (int k = lane; k < EMB; k += 32) s += wr[k] * g_emoji[k];
    #pragma unroll
    for (int off = 16; off; off >>= 1) s += __shfl_xor_sync(0xffffffffu, s, off);
    if (lane == 0) g_const2[row] = s + combB[row];
}

__global__ void k_bsum(const float* __restrict__ bih, const float* __restrict__ bhh) {
    int j = blockIdx.x * blockDim.x + threadIdx.x;
    if (j < G4) g_bsum[j] = bih[j] + bhh[j];
}

// gather word embeddings: Xb[t] = word_emb[ids[t]]
__global__ void k_gather(const int* __restrict__ ids, const float* __restrict__ emb) {
    int t = blockIdx.x;
    int id = ids[t];
    const float4* src = (const float4*)(emb + (size_t)id * EMB);
    float4* dst = (float4*)(g_Xb + (size_t)t * EMB);
    for (int i = threadIdx.x; i < EMB / 4; i += blockDim.x) dst[i] = src[i];
}

// ---------------- SIMT SGEMM:  C[M,N] = A[M,K] @ B[N,K]^T + bias[N]  (opt relu) ----------
// 128x128 tile, TK=16, 256 threads, 8x8 per thread. Both A,B K-major (row-major, K contiguous).
__global__ __launch_bounds__(256) void sgemm_nt(
    const float* __restrict__ A, int lda,
    const float* __restrict__ B, int ldb,
    const float* __restrict__ bias,
    float* __restrict__ Cc, int ldc,
    int K, int relu)
{
    __shared__ float As[16][128];
    __shared__ float Bs[16][128];

    const int tid = threadIdx.x;
    const int m0 = blockIdx.y * 128;
    const int n0 = blockIdx.x * 128;
    const int tx = tid & 15;    // n micro-tile index
    const int ty = tid >> 4;    // m micro-tile index
    const int lr = tid >> 2;    // 0..63: tile row for loads
    const int lq = tid & 3;     // k-quad for loads

    float acc[8][8];
    #pragma unroll
    for (int r = 0; r < 8; r++)
        #pragma unroll
        for (int c = 0; c < 8; c++) acc[r][c] = 0.f;

    for (int k0 = 0; k0 < K; k0 += 16) {
        #pragma unroll
        for (int s = 0; s < 2; s++) {
            int r = lr + s * 64;
            float4 va = *(const float4*)(A + (size_t)(m0 + r) * lda + k0 + lq * 4);
            As[lq * 4 + 0][r] = va.x; As[lq * 4 + 1][r] = va.y;
            As[lq * 4 + 2][r] = va.z; As[lq * 4 + 3][r] = va.w;
            float4 vb = *(const float4*)(B + (size_t)(n0 + r) * ldb + k0 + lq * 4);
            Bs[lq * 4 + 0][r] = vb.x; Bs[lq * 4 + 1][r] = vb.y;
            Bs[lq * 4 + 2][r] = vb.z; Bs[lq * 4 + 3][r] = vb.w;
        }
        __syncthreads();

        #pragma unroll
        for (int k = 0; k < 16; k++) {
            float4 a0 = *(const float4*)&As[k][ty * 8];
            float4 a1 = *(const float4*)&As[k][ty * 8 + 4];
            float4 b0 = *(const float4*)&Bs[k][tx * 8];
            float4 b1 = *(const float4*)&Bs[k][tx * 8 + 4];
            float a[8] = {a0.x, a0.y, a0.z, a0.w, a1.x, a1.y, a1.z, a1.w};
            float b[8] = {b0.x, b0.y, b0.z, b0.w, b1.x, b1.y, b1.z, b1.w};
            #pragma unroll
            for (int r = 0; r < 8; r++)
                #pragma unroll
                for (int c = 0; c < 8; c++)
                    acc[r][c] += a[r] * b[c];
        }
        __syncthreads();
    }

    #pragma unroll
    for (int r = 0; r < 8; r++) {
        int m = m0 + ty * 8 + r;
        float* cp = Cc + (size_t)m * ldc + n0 + tx * 8;
        #pragma unroll
        for (int c = 0; c < 8; c++) {
            float v = acc[r][c] + bias[n0 + tx * 8 + c];
            if (relu) v = fmaxf(v, 0.f);
            cp[c] = v;
        }
    }
}

// ---------------- persistent sequential LSTM kernel ----------------
// 128 blocks x 256 threads. Block b owns hidden units j in [b*8, b*8+8):
// 32 rows of W_hh (4 gates x 8 units) register-resident (128 floats/thread).
// One grid barrier per step (double-buffered h).
__global__ __launch_bounds__(TPB, 1) void k_seq(const float* __restrict__ Whh,
                                                const float* __restrict__ G)
{
    const int b = blockIdx.x;
    const int tid = threadIdx.x;
    const int warp = tid >> 5, lane = tid & 31;

    __shared__ float hsh[HID];
    __shared__ float gsum[32];
    __shared__ float csh[JPB];
    if (tid < JPB) csh[tid] = 0.f;

    // rows: local row lr = warp*4+rr; gate = lr>>3; jloc = lr&7; row = gate*1024 + b*8 + jloc
    int rows[4];
    float w[4][32];
    #pragma unroll
    for (int rr = 0; rr < 4; rr++) {
        int lr = warp * 4 + rr;
        int gate = lr >> 3, jloc = lr & 7;
        rows[rr] = (gate << 10) + b * JPB + jloc;
        const float* wrow = Whh + (size_t)rows[rr] * HID + lane;
        #pragma unroll
        for (int i = 0; i < 32; i++) w[rr][i] = wrow[i * 32];
    }

    for (int t = 0; t < SEQ; t++) {
        // prefetch precomputed gate terms for this step (independent of h)
        float g0 = 0.f, g1 = 0.f, g2 = 0.f, g3 = 0.f;
        if (lane == 0) {
            const float* gt = G + (size_t)t * G4;
            g0 = __ldcg(gt + rows[0]);
            g1 = __ldcg(gt + rows[1]);
            g2 = __ldcg(gt + rows[2]);
            g3 = __ldcg(gt + rows[3]);
        }

        // load h (written by other blocks last step) — bypass L1
        const float* hg = g_st.h[t & 1];
        #pragma unroll
        for (int i = 0; i < HID / TPB; i++)
            hsh[tid + i * TPB] = __ldcg(hg + tid + i * TPB);
        __syncthreads();

        float hreg[32];
        #pragma unroll
        for (int i = 0; i < 32; i++) hreg[i] = hsh[i * 32 + lane];

        float a0 = 0.f, a1 = 0.f, a2 = 0.f, a3 = 0.f;
        #pragma unroll
        for (int i = 0; i < 32; i++) {
            a0 += w[0][i] * hreg[i];
            a1 += w[1][i] * hreg[i];
            a2 += w[2][i] * hreg[i];
            a3 += w[3][i] * hreg[i];
        }
        #pragma unroll
        for (int off = 16; off; off >>= 1) {
            a0 += __shfl_xor_sync(0xffffffffu, a0, off);
            a1 += __shfl_xor_sync(0xffffffffu, a1, off);
            a2 += __shfl_xor_sync(0xffffffffu, a2, off);
            a3 += __shfl_xor_sync(0xffffffffu, a3, off);
        }
        if (lane == 0) {
            gsum[warp * 4 + 0] = a0 + g0;
            gsum[warp * 4 + 1] = a1 + g1;
            gsum[warp * 4 + 2] = a2 + g2;
            gsum[warp * 4 + 3] = a3 + g3;
        }
        __syncthreads();

        if (tid < JPB) {
            float iv = gsum[tid];            // gate 0: input
            float fv = gsum[8 + tid];        // gate 1: forget
            float gv = gsum[16 + tid];       // gate 2: cell
            float ov = gsum[24 + tid];       // gate 3: output
            float is = 1.f / (1.f + expf(-iv));
            float fs = 1.f / (1.f + expf(-fv));
            float os = 1.f / (1.f + expf(-ov));
            float cn = fs * csh[tid] + is * tanhf(gv);
            csh[tid] = cn;
            float hn = os * tanhf(cn);
            g_st.h[(t + 1) & 1][b * JPB + tid] = hn;
        }
        __syncthreads();

        // grid barrier (release h-writes, acquire others')
        if (tid == 0) {
            __threadfence();
            atomicAdd(&g_st.counter, 1u);
            unsigned target = (unsigned)(t + 1) * NB;
            while (*((volatile unsigned*)&g_st.counter) < target) { }
            __threadfence();
        }
        __syncthreads();
    }
}

// out[l] = dot(out_W[l], h_final) + out_b[l]; final h lives in buffer 0 (SEQ even)
__global__ void k_out(const float* __restrict__ outW, const float* __restrict__ outB,
                      float* __restrict__ out)
{
    int warp = threadIdx.x >> 5, lane = threadIdx.x & 31;
    if (warp < LABELS) {
        const float* wr = outW + (size_t)warp * HID;
        const float* h = g_st.h[0];
        float s = 0.f;
        for (int k = lane; k < HID; k += 32) s += wr[k] * h[k];
        #pragma unroll
        for (int off = 16; off; off >>= 1) s += __shfl_xor_sync(0xffffffffu, s, off);
        if (lane == 0) out[warp] = s + outB[warp];
    }
}

// ---------------- launch ----------------
extern "C" void kernel_launch(void* const* d_in, const int* in_sizes, int n_in,
                              void* d_out, int out_size)
{
    const int*   sids  = (const int*)  d_in[0];
    const int*   eids  = (const int*)  d_in[1];
    const float* wemb  = (const float*)d_in[2];
    const float* eemb  = (const float*)d_in[3];
    // d_in[4] attn_W, d_in[5] attn_b: mathematically dead (softmax of 1 logit == 1)
    const float* combW = (const float*)d_in[6];
    const float* combB = (const float*)d_in[7];
    const float* Wih   = (const float*)d_in[8];
    const float* Whh   = (const float*)d_in[9];
    const float* bih   = (const float*)d_in[10];
    const float* bhh   = (const float*)d_in[11];
    const float* outW  = (const float*)d_in[12];
    const float* outB  = (const float*)d_in[13];
    float* out = (float*)d_out;

    void *pXb = 0, *pC = 0, *pG = 0, *pc2 = 0, *pbs = 0;
    cudaGetSymbolAddress(&pXb, g_Xb);
    cudaGetSymbolAddress(&pC,  g_C);
    cudaGetSymbolAddress(&pG,  g_G);
    cudaGetSymbolAddress(&pc2, g_const2);
    cudaGetSymbolAddress(&pbs, g_bsum);

    k_init  <<<1, 256>>>();
    k_emoji <<<(EMB + 255) / 256, 256>>>(eids, eemb);
    k_const2<<<EMB / 8, 256>>>(combW, combB);
    k_bsum  <<<G4 / 256, 256>>>(bih, bhh);
    k_gather<<<SEQ, 256>>>(sids, wemb);

    // C = relu(Xb @ Wx^T + const2), Wx = comb_W[:, 0:EMB] (ldb = 2*EMB)
    dim3 gridC(EMB / 128, SEQ / 128);
    sgemm_nt<<<gridC, 256>>>((const float*)pXb, EMB, combW, 2 * EMB,
                             (const float*)pc2, (float*)pC, EMB, EMB, 1);

    // G = C @ W_ih^T + (b_ih + b_hh)
    dim3 gridG(G4 / 128, SEQ / 128);
    sgemm_nt<<<gridG, 256>>>((const float*)pC, EMB, Wih, EMB,
                             (const float*)pbs, (float*)pG, G4, EMB, 0);

    k_seq<<<NB, TPB>>>(Whh, (const float*)pG);
    k_out<<<1, 256>>>(outW, outB, out);
}